// round 6
// baseline (speedup 1.0000x reference)
#include <cuda_runtime.h>

// WaveFunctionDensity: rho[n,m] = sum_pq B[n,m,p] * dm[n,p,q] * B[n,m,q]
//   B[n,m,p] = dx^px * dy^py * dz^pz * exp(-alpha_p * r2[m, center_p])
//
// Shapes: n=16, ms=4096, na=32, np=512.
// CTA = (molecule, 64-sample tile), 512 threads.
//   Phase 1: build basis tile sB[512][64] in smem.
//   Phase 2: register-tiled (8m x 4q) quadratic form, dm streamed via
//            cp.async double-buffered 32x256 chunks, vectorized epilogue
//            with warp-shfl partial reduction.

#define N_MOL   16
#define MS      4096
#define NA      32
#define NP      512
#define M_TILE  64
#define Q_TILE  256
#define P_CHUNK 32
#define NCHUNK  (NP / P_CHUNK)
#define THREADS 512
#define DV_LD   65

// smem layout (floats):
//   sB   : [NP][M_TILE]          = 32768 floats (131072 B)
//   sD   : 2 x [P_CHUNK][Q_TILE] = 16384 floats ( 65536 B)
//          (phase-1 scratch aliases sD: dvT 96x65, r2 32x64)
//   sExp : 512 f, sCen/sSym : 512 i each, rho : 64 f
#define SMEM_FLOATS (32768 + 16384 + 512 + 512 + 512 + 64)
#define SMEM_BYTES  (SMEM_FLOATS * 4)

__constant__ int c_pw[20 * 3] = {
    0,0,0,
    1,0,0, 0,1,0, 0,0,1,
    2,0,0, 0,2,0, 0,0,2, 1,1,0, 1,0,1, 0,1,1,
    3,0,0, 0,3,0, 0,0,3, 2,1,0, 2,0,1, 0,2,1,
    1,2,0, 1,0,2, 0,1,2, 1,1,1
};

__device__ __forceinline__ float ipow_small(float x, int e) {
    // x^e for e in {0,1,2,3}; pow(x,0)==1 for any x (matches XLA semantics)
    float r = (e > 0 ? x : 1.0f);
    r *= (e > 1 ? x : 1.0f);
    r *= (e > 2 ? x : 1.0f);
    return r;
}

__device__ __forceinline__ void cp_async16(float* smem_dst, const float* gmem_src) {
    unsigned s = (unsigned)__cvta_generic_to_shared(smem_dst);
    asm volatile("cp.async.cg.shared.global [%0], [%1], 16;\n" :: "r"(s), "l"(gmem_src));
}
__device__ __forceinline__ void cp_async_commit() {
    asm volatile("cp.async.commit_group;\n" ::: "memory");
}
__device__ __forceinline__ void cp_async_wait1() {
    asm volatile("cp.async.wait_group 1;\n" ::: "memory");
}
__device__ __forceinline__ void cp_async_wait0() {
    asm volatile("cp.async.wait_group 0;\n" ::: "memory");
}

__global__ __launch_bounds__(THREADS, 1)
void wfn_density_kernel(const float* __restrict__ dv,
                        const int*   __restrict__ centers,
                        const float* __restrict__ exps,
                        const int*   __restrict__ syms,
                        const float* __restrict__ dm,
                        float*       __restrict__ out) {
    extern __shared__ float smem[];
    float* sB   = smem;                         // 32768 floats
    float* sD0  = smem + 32768;                 // 8192 floats
    float* sD1  = sD0 + P_CHUNK * Q_TILE;       // 8192 floats
    float* sExp = smem + 32768 + 16384;         // 512
    int*   sCen = (int*)(sExp + 512);
    int*   sSym = sCen + 512;
    float* rhoS = (float*)(sSym + 512);         // 64

    // phase-1 scratch aliases the sD buffers
    float* dvT = sD0;                  // [96][DV_LD]
    float* r2s = sD0 + 96 * DV_LD;     // [32][64]

    const int tid = threadIdx.x;
    const int n   = blockIdx.y;
    const int m0  = blockIdx.x * M_TILE;

    // ---- per-primitive params ----
    for (int i = tid; i < NP; i += THREADS) {
        sExp[i] = exps[n * NP + i];
        sCen[i] = centers[n * NP + i];
        sSym[i] = syms[n * NP + i];
    }
    if (tid < M_TILE) rhoS[tid] = 0.0f;

    // ---- dv tile, transposed ----
    const float* dvsrc = dv + ((size_t)n * MS + m0) * (NA * 3);
    for (int L = tid; L < M_TILE * NA * 3; L += THREADS) {
        int mm = L / (NA * 3);
        int t  = L % (NA * 3);
        dvT[t * DV_LD + mm] = dvsrc[L];
    }
    __syncthreads();

    // ---- r2 per (atom, sample) ----
    for (int idx = tid; idx < NA * M_TILE; idx += THREADS) {
        int a = idx >> 6, mm = idx & 63;
        float x = dvT[(a * 3 + 0) * DV_LD + mm];
        float y = dvT[(a * 3 + 1) * DV_LD + mm];
        float z = dvT[(a * 3 + 2) * DV_LD + mm];
        r2s[a * 64 + mm] = x * x + y * y + z * z;
    }
    __syncthreads();

    // ---- basis tile sB[p][mm] ----
    for (int e = tid; e < NP * M_TILE; e += THREADS) {
        int p  = e >> 6;
        int mm = e & 63;
        int c  = sCen[p];
        int cc = max(c, 0);
        float alpha = sExp[p];
        int s  = sSym[p];
        int px = c_pw[s * 3 + 0], py = c_pw[s * 3 + 1], pz = c_pw[s * 3 + 2];
        float x  = dvT[(cc * 3 + 0) * DV_LD + mm];
        float y  = dvT[(cc * 3 + 1) * DV_LD + mm];
        float z  = dvT[(cc * 3 + 2) * DV_LD + mm];
        float r2 = r2s[cc * 64 + mm];
        float ang = ipow_small(x, px) * ipow_small(y, py) * ipow_small(z, pz);
        float b = ang * __expf(-alpha * r2);
        sB[p * M_TILE + mm] = (c >= 0) ? b : 0.0f;
    }
    __syncthreads();   // phase-1 reads of sD-aliased scratch complete

    // ---- phase 2: rho[m] = sum_q B[m,q] * (sum_p B[m,p] D[p,q]) ----
    const float* Dg = dm + (size_t)n * NP * NP;
    const int tm = tid & 7;     // m-group: m = tm*8 + i, i in 0..7
    const int tq = tid >> 3;    // q-group: q = q0 + tq*4 + j, j in 0..3
    float* bufs[2] = { sD0, sD1 };

    for (int qt = 0; qt < NP / Q_TILE; ++qt) {
        float acc[8][4];
        #pragma unroll
        for (int i = 0; i < 8; ++i)
            #pragma unroll
            for (int j = 0; j < 4; ++j) acc[i][j] = 0.0f;

        const float* Dq = Dg + qt * Q_TILE;

        // prologue: async-load chunk 0 into buf 0
        {
            #pragma unroll
            for (int v = tid; v < P_CHUNK * Q_TILE / 4; v += THREADS) {
                int row = v >> 6;
                int c4  = v & 63;
                cp_async16(&bufs[0][row * Q_TILE + c4 * 4],
                           &Dq[(size_t)row * NP + c4 * 4]);
            }
            cp_async_commit();
        }

        for (int ic = 0; ic < NCHUNK; ++ic) {
            if (ic + 1 < NCHUNK) {
                float* b = bufs[(ic + 1) & 1];
                const float* src = Dq + (size_t)(ic + 1) * P_CHUNK * NP;
                #pragma unroll
                for (int v = tid; v < P_CHUNK * Q_TILE / 4; v += THREADS) {
                    int row = v >> 6;
                    int c4  = v & 63;
                    cp_async16(&b[row * Q_TILE + c4 * 4],
                               &src[(size_t)row * NP + c4 * 4]);
                }
                cp_async_commit();
                cp_async_wait1();   // chunk ic resident
            } else {
                cp_async_wait0();
            }
            __syncthreads();

            const float* sD = bufs[ic & 1];
            const int pc = ic * P_CHUNK;
            #pragma unroll 4
            for (int pp = 0; pp < P_CHUNK; ++pp) {
                float4 b0 = *(const float4*)&sB[(pc + pp) * M_TILE + tm * 8];
                float4 b1 = *(const float4*)&sB[(pc + pp) * M_TILE + tm * 8 + 4];
                float4 d0 = *(const float4*)&sD[pp * Q_TILE + tq * 4];
                float bb[8] = {b0.x, b0.y, b0.z, b0.w, b1.x, b1.y, b1.z, b1.w};
                float dd[4] = {d0.x, d0.y, d0.z, d0.w};
                #pragma unroll
                for (int i = 0; i < 8; ++i)
                    #pragma unroll
                    for (int j = 0; j < 4; ++j)
                        acc[i][j] = fmaf(bb[i], dd[j], acc[i][j]);
            }
            __syncthreads();   // readers done before this buffer is refilled
        }

        // epilogue: partial[i] = sum_j acc[i][j] * B[q_j, m_i], vectorized reads
        float part[8];
        #pragma unroll
        for (int i = 0; i < 8; ++i) part[i] = 0.0f;
        #pragma unroll
        for (int j = 0; j < 4; ++j) {
            int q = qt * Q_TILE + tq * 4 + j;
            float4 c0 = *(const float4*)&sB[q * M_TILE + tm * 8];
            float4 c1 = *(const float4*)&sB[q * M_TILE + tm * 8 + 4];
            part[0] = fmaf(acc[0][j], c0.x, part[0]);
            part[1] = fmaf(acc[1][j], c0.y, part[1]);
            part[2] = fmaf(acc[2][j], c0.z, part[2]);
            part[3] = fmaf(acc[3][j], c0.w, part[3]);
            part[4] = fmaf(acc[4][j], c1.x, part[4]);
            part[5] = fmaf(acc[5][j], c1.y, part[5]);
            part[6] = fmaf(acc[6][j], c1.z, part[6]);
            part[7] = fmaf(acc[7][j], c1.w, part[7]);
        }
        // reduce across the 4 lanes in this warp that share tm (lane ^ 8, ^ 16)
        #pragma unroll
        for (int i = 0; i < 8; ++i) {
            part[i] += __shfl_xor_sync(0xFFFFFFFFu, part[i], 8);
            part[i] += __shfl_xor_sync(0xFFFFFFFFu, part[i], 16);
        }
        if (((tid >> 3) & 3) == 0) {   // one lane per tm-group per warp
            #pragma unroll
            for (int i = 0; i < 8; ++i)
                atomicAdd(&rhoS[tm * 8 + i], part[i]);
        }
    }

    __syncthreads();
    if (tid < M_TILE)
        out[(size_t)n * MS + m0 + tid] = rhoS[tid];
}

extern "C" void kernel_launch(void* const* d_in, const int* in_sizes, int n_in,
                              void* d_out, int out_size) {
    const float* dv      = (const float*)d_in[0];
    const int*   centers = (const int*)  d_in[1];
    const float* exps    = (const float*)d_in[2];
    const int*   syms    = (const int*)  d_in[3];
    const float* dm      = (const float*)d_in[4];
    float* out = (float*)d_out;

    cudaFuncSetAttribute(wfn_density_kernel,
                         cudaFuncAttributeMaxDynamicSharedMemorySize, SMEM_BYTES);

    dim3 grid(MS / M_TILE, N_MOL);
    wfn_density_kernel<<<grid, THREADS, SMEM_BYTES>>>(dv, centers, exps, syms, dm, out);
}

// round 8
// speedup vs baseline: 1.6046x; 1.6046x over previous
#include <cuda_runtime.h>

// WaveFunctionDensity: rho[n,m] = sum_pq B[n,m,p] * dm[n,p,q] * B[n,m,q]
//   B[n,m,p] = dx^px * dy^py * dz^pz * exp(-alpha_p * r2[m, center_p])
//
// Shapes: n=16, ms=4096, na=32, np=512.
// CTA = (molecule, 64-sample tile), 256 threads.
//   Phase 1: build basis tile sB[512][64] in smem.
//   Phase 2: register-tiled 16m x 8q quadratic form over the FULL q range
//            (no q-tiling); dm streamed via cp.async double-buffered
//            16x512 contiguous chunks.

#define N_MOL   16
#define MS      4096
#define NA      32
#define NP      512
#define M_TILE  64
#define P_CHUNK 16
#define NCHUNK  (NP / P_CHUNK)
#define THREADS 256
#define DV_LD   65

// smem layout (floats):
//   sB   : [NP][M_TILE]          = 32768 floats (131072 B)
//   sD   : 2 x [P_CHUNK][NP]     = 16384 floats ( 65536 B)
//          (phase-1 scratch aliases sD: dvT 96x65, r2 32x64)
//   sExp : 512 f, sCen/sSym : 512 i each, rho : 64 f
#define SMEM_FLOATS (32768 + 16384 + 512 + 512 + 512 + 64)
#define SMEM_BYTES  (SMEM_FLOATS * 4)

__constant__ int c_pw[20 * 3] = {
    0,0,0,
    1,0,0, 0,1,0, 0,0,1,
    2,0,0, 0,2,0, 0,0,2, 1,1,0, 1,0,1, 0,1,1,
    3,0,0, 0,3,0, 0,0,3, 2,1,0, 2,0,1, 0,2,1,
    1,2,0, 1,0,2, 0,1,2, 1,1,1
};

__device__ __forceinline__ float ipow_small(float x, int e) {
    // x^e for e in {0,1,2,3}; pow(x,0)==1 for any x (matches XLA semantics)
    float r = (e > 0 ? x : 1.0f);
    r *= (e > 1 ? x : 1.0f);
    r *= (e > 2 ? x : 1.0f);
    return r;
}

__device__ __forceinline__ void cp_async16(float* smem_dst, const float* gmem_src) {
    unsigned s = (unsigned)__cvta_generic_to_shared(smem_dst);
    asm volatile("cp.async.cg.shared.global [%0], [%1], 16;\n" :: "r"(s), "l"(gmem_src));
}
__device__ __forceinline__ void cp_async_commit() {
    asm volatile("cp.async.commit_group;\n" ::: "memory");
}
__device__ __forceinline__ void cp_async_wait1() {
    asm volatile("cp.async.wait_group 1;\n" ::: "memory");
}
__device__ __forceinline__ void cp_async_wait0() {
    asm volatile("cp.async.wait_group 0;\n" ::: "memory");
}

__global__ __launch_bounds__(THREADS, 1)
void wfn_density_kernel(const float* __restrict__ dv,
                        const int*   __restrict__ centers,
                        const float* __restrict__ exps,
                        const int*   __restrict__ syms,
                        const float* __restrict__ dm,
                        float*       __restrict__ out) {
    extern __shared__ float smem[];
    float* sB   = smem;                         // 32768 floats
    float* sD0  = smem + 32768;                 // 8192 floats (16x512)
    float* sD1  = sD0 + P_CHUNK * NP;           // 8192 floats
    float* sExp = smem + 32768 + 16384;         // 512
    int*   sCen = (int*)(sExp + 512);
    int*   sSym = sCen + 512;
    float* rhoS = (float*)(sSym + 512);         // 64

    // phase-1 scratch spans sD0 (+ start of sD1): 6240 + 2048 floats
    float* dvT = sD0;                  // [96][DV_LD]
    float* r2s = sD0 + 96 * DV_LD;     // [32][64]

    const int tid = threadIdx.x;
    const int n   = blockIdx.y;
    const int m0  = blockIdx.x * M_TILE;

    // ---- per-primitive params ----
    for (int i = tid; i < NP; i += THREADS) {
        sExp[i] = exps[n * NP + i];
        sCen[i] = centers[n * NP + i];
        sSym[i] = syms[n * NP + i];
    }
    if (tid < M_TILE) rhoS[tid] = 0.0f;

    // ---- dv tile, transposed ----
    const float* dvsrc = dv + ((size_t)n * MS + m0) * (NA * 3);
    for (int L = tid; L < M_TILE * NA * 3; L += THREADS) {
        int mm = L / (NA * 3);
        int t  = L % (NA * 3);
        dvT[t * DV_LD + mm] = dvsrc[L];
    }
    __syncthreads();

    // ---- r2 per (atom, sample) ----
    for (int idx = tid; idx < NA * M_TILE; idx += THREADS) {
        int a = idx >> 6, mm = idx & 63;
        float x = dvT[(a * 3 + 0) * DV_LD + mm];
        float y = dvT[(a * 3 + 1) * DV_LD + mm];
        float z = dvT[(a * 3 + 2) * DV_LD + mm];
        r2s[a * 64 + mm] = x * x + y * y + z * z;
    }
    __syncthreads();

    // ---- basis tile sB[p][mm] ----
    for (int e = tid; e < NP * M_TILE; e += THREADS) {
        int p  = e >> 6;
        int mm = e & 63;
        int c  = sCen[p];
        int cc = max(c, 0);
        float alpha = sExp[p];
        int s  = sSym[p];
        int px = c_pw[s * 3 + 0], py = c_pw[s * 3 + 1], pz = c_pw[s * 3 + 2];
        float x  = dvT[(cc * 3 + 0) * DV_LD + mm];
        float y  = dvT[(cc * 3 + 1) * DV_LD + mm];
        float z  = dvT[(cc * 3 + 2) * DV_LD + mm];
        float r2 = r2s[cc * 64 + mm];
        float ang = ipow_small(x, px) * ipow_small(y, py) * ipow_small(z, pz);
        float b = ang * __expf(-alpha * r2);
        sB[p * M_TILE + mm] = (c >= 0) ? b : 0.0f;
    }
    __syncthreads();   // phase-1 reads of sD-aliased scratch complete

    // ---- phase 2: acc[m, q] = sum_p B[m,p] D[p,q]  (16m x 8q per thread) ----
    const float* Dg = dm + (size_t)n * NP * NP;
    const int tm = tid & 3;     // m-group: m = tm*16 + i, i in 0..15
    const int tq = tid >> 2;    // q-group: q = tq*8 + j, j in 0..7
    float* bufs[2] = { sD0, sD1 };

    float acc[16][8];
    #pragma unroll
    for (int i = 0; i < 16; ++i)
        #pragma unroll
        for (int j = 0; j < 8; ++j) acc[i][j] = 0.0f;

    // prologue: chunk 0 (contiguous 16x512 region)
    {
        const float* src = Dg;
        #pragma unroll
        for (int v = tid; v < P_CHUNK * NP / 4; v += THREADS)
            cp_async16(&bufs[0][v * 4], &src[v * 4]);
        cp_async_commit();
    }

    for (int ic = 0; ic < NCHUNK; ++ic) {
        if (ic + 1 < NCHUNK) {
            float* b = bufs[(ic + 1) & 1];
            const float* src = Dg + (size_t)(ic + 1) * P_CHUNK * NP;
            #pragma unroll
            for (int v = tid; v < P_CHUNK * NP / 4; v += THREADS)
                cp_async16(&b[v * 4], &src[v * 4]);
            cp_async_commit();
            cp_async_wait1();   // chunk ic resident
        } else {
            cp_async_wait0();
        }
        __syncthreads();

        const float* sD = bufs[ic & 1];
        const int pc = ic * P_CHUNK;
        #pragma unroll 2
        for (int pp = 0; pp < P_CHUNK; ++pp) {
            const float* brow = &sB[(pc + pp) * M_TILE + tm * 16];
            float4 b0 = *(const float4*)&brow[0];
            float4 b1 = *(const float4*)&brow[4];
            float4 b2 = *(const float4*)&brow[8];
            float4 b3 = *(const float4*)&brow[12];
            const float* drow = &sD[pp * NP + tq * 8];
            float4 d0 = *(const float4*)&drow[0];
            float4 d1 = *(const float4*)&drow[4];
            float bb[16] = {b0.x, b0.y, b0.z, b0.w, b1.x, b1.y, b1.z, b1.w,
                            b2.x, b2.y, b2.z, b2.w, b3.x, b3.y, b3.z, b3.w};
            float dd[8]  = {d0.x, d0.y, d0.z, d0.w, d1.x, d1.y, d1.z, d1.w};
            #pragma unroll
            for (int i = 0; i < 16; ++i)
                #pragma unroll
                for (int j = 0; j < 8; ++j)
                    acc[i][j] = fmaf(bb[i], dd[j], acc[i][j]);
        }
        __syncthreads();   // readers done before this buffer is refilled
    }

    // ---- epilogue: part[i] = sum_j acc[i][j] * B[q_j, m_i] ----
    float part[16];
    #pragma unroll
    for (int i = 0; i < 16; ++i) part[i] = 0.0f;
    #pragma unroll
    for (int j = 0; j < 8; ++j) {
        int q = tq * 8 + j;
        const float* col = &sB[q * M_TILE + tm * 16];
        float4 c0 = *(const float4*)&col[0];
        float4 c1 = *(const float4*)&col[4];
        float4 c2 = *(const float4*)&col[8];
        float4 c3 = *(const float4*)&col[12];
        float cc[16] = {c0.x, c0.y, c0.z, c0.w, c1.x, c1.y, c1.z, c1.w,
                        c2.x, c2.y, c2.z, c2.w, c3.x, c3.y, c3.z, c3.w};
        #pragma unroll
        for (int i = 0; i < 16; ++i)
            part[i] = fmaf(acc[i][j], cc[i], part[i]);
    }
    // reduce across the 8 lanes in this warp that share tm (lane bits 2,3,4)
    #pragma unroll
    for (int i = 0; i < 16; ++i) {
        part[i] += __shfl_xor_sync(0xFFFFFFFFu, part[i], 4);
        part[i] += __shfl_xor_sync(0xFFFFFFFFu, part[i], 8);
        part[i] += __shfl_xor_sync(0xFFFFFFFFu, part[i], 16);
    }
    if (((tid >> 2) & 7) == 0) {   // one lane per tm-group per warp
        #pragma unroll
        for (int i = 0; i < 16; ++i)
            atomicAdd(&rhoS[tm * 16 + i], part[i]);
    }

    __syncthreads();
    if (tid < M_TILE)
        out[(size_t)n * MS + m0 + tid] = rhoS[tid];
}

extern "C" void kernel_launch(void* const* d_in, const int* in_sizes, int n_in,
                              void* d_out, int out_size) {
    const float* dv      = (const float*)d_in[0];
    const int*   centers = (const int*)  d_in[1];
    const float* exps    = (const float*)d_in[2];
    const int*   syms    = (const int*)  d_in[3];
    const float* dm      = (const float*)d_in[4];
    float* out = (float*)d_out;

    cudaFuncSetAttribute(wfn_density_kernel,
                         cudaFuncAttributeMaxDynamicSharedMemorySize, SMEM_BYTES);

    dim3 grid(MS / M_TILE, N_MOL);
    wfn_density_kernel<<<grid, THREADS, SMEM_BYTES>>>(dv, centers, exps, syms, dm, out);
}